// round 3
// baseline (speedup 1.0000x reference)
#include <cuda_runtime.h>
#include <cstdint>
#include <cstddef>

#define BB 8
#define NN 16384
#define MM 256
#define CC 128
#define NS 32
#define FPS_T 512
#define CLU 8                 /* cluster size: CTAs per batch */

/* output layout (concatenated, float32) */
#define GP_OFF 0                      /* grouped_p [8,3,256,32]  */
#define CP_OFF 196608                 /* center_p  [8,256,3]     */
#define FJ_OFF 202752                 /* fj        [8,128,256,32]*/
#define CX_OFF 8591360                /* center_x  [8,128,256,1] */

__device__ int g_fpsidx[BB * MM];
__device__ int g_nidx[BB * MM * NS];

/* ---------- exact-rounding f32x2 helpers (no FMA contraction) ---------- */
__device__ __forceinline__ unsigned long long pk2(float lo, float hi) {
    unsigned long long r;
    asm("mov.b64 %0, {%1,%2};" : "=l"(r) : "f"(lo), "f"(hi));
    return r;
}
__device__ __forceinline__ float2 upk2(unsigned long long v) {
    float2 r;
    asm("mov.b64 {%0,%1}, %2;" : "=f"(r.x), "=f"(r.y) : "l"(v));
    return r;
}
__device__ __forceinline__ unsigned long long add2(unsigned long long a, unsigned long long b) {
    unsigned long long r;
    asm("add.rn.f32x2 %0, %1, %2;" : "=l"(r) : "l"(a), "l"(b));
    return r;
}
__device__ __forceinline__ unsigned long long mul2(unsigned long long a, unsigned long long b) {
    unsigned long long r;
    asm("mul.rn.f32x2 %0, %1, %2;" : "=l"(r) : "l"(a), "l"(b));
    return r;
}
__device__ __forceinline__ uint32_t smem_u32(const void* p) {
    uint32_t a;
    asm("{ .reg .u64 t; cvta.to.shared.u64 t, %1; cvt.u32.u64 %0, t; }"
        : "=r"(a) : "l"(p));
    return a;
}
__device__ __forceinline__ uint32_t mapa_u32(uint32_t local, uint32_t rank) {
    uint32_t r;
    asm("mapa.shared::cluster.u32 %0, %1, %2;" : "=r"(r) : "r"(local), "r"(rank));
    return r;
}
__device__ __forceinline__ void st_clu64(uint32_t addr, unsigned long long v) {
    asm volatile("st.shared::cluster.u64 [%0], %1;" :: "r"(addr), "l"(v) : "memory");
}
__device__ __forceinline__ void mbar_init(uint32_t addr, uint32_t count) {
    asm volatile("mbarrier.init.shared.b64 [%0], %1;" :: "r"(addr), "r"(count) : "memory");
}
__device__ __forceinline__ void mbar_arrive_remote(uint32_t addr) {
    asm volatile("mbarrier.arrive.release.cluster.shared::cluster.b64 _, [%0];"
                 :: "r"(addr) : "memory");
}
__device__ __forceinline__ void mbar_wait(uint32_t addr, uint32_t parity) {
    uint32_t done;
    asm volatile(
        "{\n\t.reg .pred p;\n\t"
        "mbarrier.try_wait.parity.acquire.cluster.shared::cta.b64 p, [%1], %2;\n\t"
        "selp.b32 %0, 1, 0, p;\n\t}"
        : "=r"(done) : "r"(addr), "r"(parity) : "memory");
    if (!done) {
        asm volatile(
            "{\n\t.reg .pred P1;\n\t"
            "WAIT_LOOP_%=:\n\t"
            "mbarrier.try_wait.parity.acquire.cluster.shared::cta.b64 P1, [%0], %1, 0x989680;\n\t"
            "@P1 bra.uni WAIT_DONE_%=;\n\t"
            "bra.uni WAIT_LOOP_%=;\n\t"
            "WAIT_DONE_%=:\n\t}"
            :: "r"(addr), "r"(parity) : "memory");
    }
}
/* key = (bits(d)<<32) | ~idx : max-key == (max d, first index on ties) */
__device__ __forceinline__ unsigned long long mkkey(float d, unsigned idx) {
    return ((unsigned long long)__float_as_uint(d) << 32) | (unsigned long long)(~idx);
}

/* =======================================================================
 * Kernel 1: FPS, cluster-distributed, u64-key reduce, mbarrier handoff.
 * 8 CTAs/batch x 512 thr x 4 points. Per iter:
 *   packed exact dist update -> local argmax -> warp xor-reduce (u64 key)
 *   -> leaders STS -> sync -> all threads reduce 16 keys; owner thread
 *   publishes coords -> sync -> threads 0..7 push (key,x,y,z) to rank=t
 *   slot + remote mbarrier arrive (double-buffered) -> local mbar wait
 *   -> all threads reduce 8 slots -> new center.
 * ===================================================================== */
__global__ void __launch_bounds__(FPS_T, 1) __cluster_dims__(CLU, 1, 1)
fps_kernel(const float* __restrict__ p, float* __restrict__ out)
{
    __shared__ unsigned long long skeys[16];
    __shared__ unsigned long long slots[2][CLU][3];  /* key, (x,y), (z,-) */
    __shared__ alignas(8) unsigned long long mbar[2];
    __shared__ float s_cc[3];

    const int t = threadIdx.x;
    const int r = blockIdx.x & (CLU - 1);
    const int b = blockIdx.x / CLU;
    const int w = t >> 5, lane = t & 31;
    const unsigned nbase = (unsigned)(r * (NN / CLU) + t);   /* +k*512 */
    const float* __restrict__ pb = p + (size_t)b * NN * 3;
    float* __restrict__ centerP = out + CP_OFF;

    if (t == 0) { mbar_init(smem_u32(&mbar[0]), CLU); mbar_init(smem_u32(&mbar[1]), CLU); }

    /* coords in registers: pairs (k0,k1), (k2,k3) */
    unsigned long long X[2], Y[2], Z[2];
#pragma unroll
    for (int q = 0; q < 2; q++) {
        int n0 = (int)nbase + (2 * q) * FPS_T;
        int n1 = n0 + FPS_T;
        X[q] = pk2(pb[n0 * 3 + 0], pb[n1 * 3 + 0]);
        Y[q] = pk2(pb[n0 * 3 + 1], pb[n1 * 3 + 1]);
        Z[q] = pk2(pb[n0 * 3 + 2], pb[n1 * 3 + 2]);
    }
    float d0 = 1e10f, d1 = 1e10f, d2 = 1e10f, d3 = 1e10f;

    /* remote slot/barrier addresses for pusher role (rank = t&7) */
    uint32_t rslot[2], rbar[2];
#pragma unroll
    for (int q = 0; q < 2; q++) {
        rslot[q] = mapa_u32(smem_u32(&slots[q][r][0]), (uint32_t)(t & 7));
        rbar[q]  = mapa_u32(smem_u32(&mbar[q]),        (uint32_t)(t & 7));
    }

    float cx = pb[0], cy = pb[1], cz = pb[2];      /* center 0 = point 0 */
    if (r == 0 && t == 0) {
        g_fpsidx[b * MM + 0] = 0;
        centerP[(b * MM + 0) * 3 + 0] = cx;
        centerP[(b * MM + 0) * 3 + 1] = cy;
        centerP[(b * MM + 0) * 3 + 2] = cz;
    }

    /* mbarrier init must be cluster-visible before first remote arrive */
    asm volatile("barrier.cluster.arrive.aligned;" ::: "memory");
    asm volatile("barrier.cluster.wait.aligned;" ::: "memory");

    for (int m = 1; m < MM; m++) {
        const unsigned long long ncx = pk2(-cx, -cx);
        const unsigned long long ncy = pk2(-cy, -cy);
        const unsigned long long ncz = pk2(-cz, -cz);

        /* exact packed distance update: ((dx*dx+dy*dy)+dz*dz), then min */
        {
            unsigned long long dx = add2(X[0], ncx);
            unsigned long long dy = add2(Y[0], ncy);
            unsigned long long dz = add2(Z[0], ncz);
            float2 dv = upk2(add2(add2(mul2(dx, dx), mul2(dy, dy)), mul2(dz, dz)));
            d0 = fminf(d0, dv.x); d1 = fminf(d1, dv.y);
        }
        {
            unsigned long long dx = add2(X[1], ncx);
            unsigned long long dy = add2(Y[1], ncy);
            unsigned long long dz = add2(Z[1], ncz);
            float2 dv = upk2(add2(add2(mul2(dx, dx), mul2(dy, dy)), mul2(dz, dz)));
            d2 = fminf(d2, dv.x); d3 = fminf(d3, dv.y);
        }

        /* thread-local argmax over 4 (ascending k keeps first-max) */
        float bv = d0; int bk = 0;
        if (d1 > bv) { bv = d1; bk = 1; }
        if (d2 > bv) { bv = d2; bk = 2; }
        if (d3 > bv) { bv = d3; bk = 3; }
        unsigned long long key = mkkey(bv, nbase + (unsigned)bk * FPS_T);

        /* warp xor-reduce: every lane ends with warp-max key */
#pragma unroll
        for (int off = 16; off > 0; off >>= 1) {
            unsigned long long o = __shfl_xor_sync(0xffffffffu, key, off);
            if (o > key) key = o;
        }
        if (lane == 0) skeys[w] = key;
        __syncthreads();

        /* all threads reduce the 16 warp keys (broadcast LDS, tree) */
        unsigned long long a[16];
#pragma unroll
        for (int j = 0; j < 16; j++) a[j] = skeys[j];
#pragma unroll
        for (int s = 8; s > 0; s >>= 1)
#pragma unroll
            for (int j = 0; j < 8; j++)
                if (j < s && a[j + s] > a[j]) a[j] = a[j + s];
        const unsigned long long ctakey = a[0];

        /* unique owner thread publishes the CTA winner's coords */
        {
            unsigned cidx = ~(unsigned)(uint32_t)ctakey;
            if ((cidx >> 11) == (unsigned)r && (cidx & 511u) == (unsigned)t) {
                int k = (cidx >> 9) & 3;
                float2 fx = (k < 2) ? upk2(X[0]) : upk2(X[1]);
                float2 fy = (k < 2) ? upk2(Y[0]) : upk2(Y[1]);
                float2 fz = (k < 2) ? upk2(Z[0]) : upk2(Z[1]);
                s_cc[0] = (k & 1) ? fx.y : fx.x;
                s_cc[1] = (k & 1) ? fy.y : fy.x;
                s_cc[2] = (k & 1) ? fz.y : fz.x;
            }
        }
        __syncthreads();

        /* threads 0..7: push (key, coords) to rank=t, arrive remote mbar */
        const int q = m & 1;
        if (t < 8) {
            st_clu64(rslot[q],      ctakey);
            st_clu64(rslot[q] + 8,  pk2(s_cc[0], s_cc[1]));
            st_clu64(rslot[q] + 16, pk2(s_cc[2], 0.f));
            mbar_arrive_remote(rbar[q]);
        }

        /* wait for all 8 ranks' pushes (parity per buffer use count) */
        const uint32_t parity = (uint32_t)(((m >> 1) + (m & 1) + 1) & 1);
        mbar_wait(smem_u32(&mbar[q]), parity);

        /* reduce 8 slots: tree max on keys, then pick winner's coords */
        unsigned long long kk[8];
#pragma unroll
        for (int j = 0; j < 8; j++) kk[j] = slots[q][j][0];
        unsigned long long wkey = kk[0];
#pragma unroll
        for (int j = 1; j < 8; j++) if (kk[j] > wkey) wkey = kk[j];
        int ws = 0;
#pragma unroll
        for (int j = 7; j >= 1; j--) if (kk[j] == wkey) ws = j;
        float2 xy = upk2(slots[q][ws][1]);
        float2 zp = upk2(slots[q][ws][2]);
        cx = xy.x; cy = xy.y; cz = zp.x;

        if (r == 0 && t == 0) {
            int wi = (int)(~(unsigned)(uint32_t)wkey);
            g_fpsidx[b * MM + m] = wi;
            centerP[(b * MM + m) * 3 + 0] = cx;
            centerP[(b * MM + m) * 3 + 1] = cy;
            centerP[(b * MM + m) * 3 + 2] = cz;
        }
    }

    /* drain: no CTA exits while peers' remote ops could be in flight */
    asm volatile("barrier.cluster.arrive.aligned;" ::: "memory");
    asm volatile("barrier.cluster.wait.aligned;" ::: "memory");
}

/* =======================================================================
 * Kernel 2: ball query, warp per center. 4 chunks (128 pts) per exit
 * check; ballot + prefix-popc ordered append; pad with first neighbor.
 * Also writes grouped_p (= p[nidx]-center), exact __fsub_rn.
 * ===================================================================== */
__global__ void __launch_bounds__(256)
ballquery_kernel(const float* __restrict__ p, float* __restrict__ out)
{
    __shared__ int sidx[8][NS];
    const int lane = threadIdx.x & 31;
    const int wloc = threadIdx.x >> 5;
    const int gw   = blockIdx.x * 8 + wloc;
    const int b = gw >> 8;
    const int m = gw & (MM - 1);

    const float* __restrict__ centerP = out + CP_OFF;
    const float cx = centerP[(b * MM + m) * 3 + 0];
    const float cy = centerP[(b * MM + m) * 3 + 1];
    const float cz = centerP[(b * MM + m) * 3 + 2];
    const float R2 = 0.01f;

    const float* __restrict__ pb = p + (size_t)b * NN * 3;

    int cnt = 0;
    for (int base = 0; base < NN && cnt < NS; base += 128) {
        unsigned msk[4];
#pragma unroll
        for (int j = 0; j < 4; j++) {
            const int n = base + j * 32 + lane;
            const float dx = __fsub_rn(cx, pb[n * 3 + 0]);
            const float dy = __fsub_rn(cy, pb[n * 3 + 1]);
            const float dz = __fsub_rn(cz, pb[n * 3 + 2]);
            const float d2 = __fadd_rn(__fadd_rn(__fmul_rn(dx, dx), __fmul_rn(dy, dy)),
                                       __fmul_rn(dz, dz));
            msk[j] = __ballot_sync(0xffffffffu, d2 < R2);
        }
#pragma unroll
        for (int j = 0; j < 4; j++) {
            const int n = base + j * 32 + lane;
            const bool in = (msk[j] >> lane) & 1u;
            const int pos = cnt + __popc(msk[j] & ((1u << lane) - 1u));
            if (in && pos < NS) sidx[wloc][pos] = n;
            cnt += __popc(msk[j]);
        }
    }
    if (cnt > NS) cnt = NS;
    __syncwarp();

    const int first = sidx[wloc][0];
    const int myidx = (lane < cnt) ? sidx[wloc][lane] : first;
    g_nidx[(b * MM + m) * NS + lane] = myidx;

    const float gx = pb[myidx * 3 + 0];
    const float gy = pb[myidx * 3 + 1];
    const float gz = pb[myidx * 3 + 2];
    float* __restrict__ gp = out + GP_OFF;
    gp[((size_t)(b * 3 + 0) * MM + m) * NS + lane] = __fsub_rn(gx, cx);
    gp[((size_t)(b * 3 + 1) * MM + m) * NS + lane] = __fsub_rn(gy, cy);
    gp[((size_t)(b * 3 + 2) * MM + m) * NS + lane] = __fsub_rn(gz, cz);
}

/* =======================================================================
 * Kernel 3: feature gathers. Block per (b,m); 8 channels x 32 samples
 * per step, 16 steps over C=128. Coalesced fj writes.
 * ===================================================================== */
__global__ void __launch_bounds__(256)
gather_kernel(const float* __restrict__ x, float* __restrict__ out)
{
    __shared__ int sidx[NS];
    __shared__ int scidx;
    const int bm = blockIdx.x;
    const int b  = bm >> 8;
    const int m  = bm & (MM - 1);
    const int tid = threadIdx.x;

    if (tid < NS) sidx[tid] = g_nidx[bm * NS + tid];
    if (tid == 0) scidx = g_fpsidx[bm];
    __syncthreads();

    const int s  = tid & 31;
    const int cl = tid >> 5;
    const float* __restrict__ xb = x + (size_t)b * CC * NN;
    float* __restrict__ fj = out + FJ_OFF;
    float* __restrict__ cxo = out + CX_OFF;
    const int ci = scidx;
    const int myn = sidx[s];

#pragma unroll
    for (int rr = 0; rr < 16; rr++) {
        const int c = rr * 8 + cl;
        const float* __restrict__ row = xb + (size_t)c * NN;
        fj[(((size_t)(b * CC + c) * MM + m) << 5) + s] = __ldg(row + myn);
        if (s == 0)
            cxo[(size_t)(b * CC + c) * MM + m] = __ldg(row + ci);
    }
}

/* ======================================================================= */
extern "C" void kernel_launch(void* const* d_in, const int* in_sizes, int n_in,
                              void* d_out, int out_size)
{
    const float* p = (const float*)d_in[0];
    const float* x = (const float*)d_in[1];
    if (n_in >= 2 && in_sizes[0] > in_sizes[1]) {
        p = (const float*)d_in[1];
        x = (const float*)d_in[0];
    }
    float* out = (float*)d_out;

    fps_kernel<<<BB * CLU, FPS_T>>>(p, out);
    ballquery_kernel<<<(BB * MM) / 8, 256>>>(p, out);
    gather_kernel<<<BB * MM, 256>>>(x, out);
}

// round 4
// speedup vs baseline: 1.1485x; 1.1485x over previous
#include <cuda_runtime.h>
#include <cstdint>
#include <cstddef>

#define BB 8
#define NN 16384
#define MM 256
#define CC 128
#define NS 32
#define FPS_T 512
#define CLU 8                 /* cluster size: CTAs per batch */

/* output layout (concatenated, float32) */
#define GP_OFF 0                      /* grouped_p [8,3,256,32]  */
#define CP_OFF 196608                 /* center_p  [8,256,3]     */
#define FJ_OFF 202752                 /* fj        [8,128,256,32]*/
#define CX_OFF 8591360                /* center_x  [8,128,256,1] */

__device__ int g_fpsidx[BB * MM];
__device__ int g_nidx[BB * MM * NS];

/* ---------- exact-rounding f32x2 helpers (no FMA contraction) ---------- */
__device__ __forceinline__ unsigned long long pk2(float lo, float hi) {
    unsigned long long r;
    asm("mov.b64 %0, {%1,%2};" : "=l"(r) : "f"(lo), "f"(hi));
    return r;
}
__device__ __forceinline__ float2 upk2(unsigned long long v) {
    float2 r;
    asm("mov.b64 {%0,%1}, %2;" : "=f"(r.x), "=f"(r.y) : "l"(v));
    return r;
}
__device__ __forceinline__ unsigned long long add2(unsigned long long a, unsigned long long b) {
    unsigned long long r;
    asm("add.rn.f32x2 %0, %1, %2;" : "=l"(r) : "l"(a), "l"(b));
    return r;
}
__device__ __forceinline__ unsigned long long mul2(unsigned long long a, unsigned long long b) {
    unsigned long long r;
    asm("mul.rn.f32x2 %0, %1, %2;" : "=l"(r) : "l"(a), "l"(b));
    return r;
}
__device__ __forceinline__ uint32_t smem_u32(const void* p) {
    uint32_t a;
    asm("{ .reg .u64 t; cvta.to.shared.u64 t, %1; cvt.u32.u64 %0, t; }"
        : "=r"(a) : "l"(p));
    return a;
}
__device__ __forceinline__ uint32_t mapa_u32(uint32_t local, uint32_t rank) {
    uint32_t r;
    asm("mapa.shared::cluster.u32 %0, %1, %2;" : "=r"(r) : "r"(local), "r"(rank));
    return r;
}
__device__ __forceinline__ void st_clu64(uint32_t addr, unsigned long long v) {
    asm volatile("st.shared::cluster.u64 [%0], %1;" :: "r"(addr), "l"(v) : "memory");
}
__device__ __forceinline__ void mbar_init(uint32_t addr, uint32_t count) {
    asm volatile("mbarrier.init.shared.b64 [%0], %1;" :: "r"(addr), "r"(count) : "memory");
}
__device__ __forceinline__ void mbar_arrive_remote(uint32_t addr) {
    asm volatile("mbarrier.arrive.release.cluster.shared::cluster.b64 _, [%0];"
                 :: "r"(addr) : "memory");
}
__device__ __forceinline__ void mbar_wait(uint32_t addr, uint32_t parity) {
    uint32_t done;
    asm volatile(
        "{\n\t.reg .pred p;\n\t"
        "mbarrier.try_wait.parity.acquire.cluster.shared::cta.b64 p, [%1], %2;\n\t"
        "selp.b32 %0, 1, 0, p;\n\t}"
        : "=r"(done) : "r"(addr), "r"(parity) : "memory");
    if (!done) {
        asm volatile(
            "{\n\t.reg .pred P1;\n\t"
            "WAIT_LOOP_%=:\n\t"
            "mbarrier.try_wait.parity.acquire.cluster.shared::cta.b64 P1, [%0], %1, 0x989680;\n\t"
            "@P1 bra.uni WAIT_DONE_%=;\n\t"
            "bra.uni WAIT_LOOP_%=;\n\t"
            "WAIT_DONE_%=:\n\t}"
            :: "r"(addr), "r"(parity) : "memory");
    }
}
/* key = (bits(d)<<32) | ~idx : max-key == (max d, first index on ties) */
__device__ __forceinline__ unsigned long long mkkey(float d, unsigned idx) {
    return ((unsigned long long)__float_as_uint(d) << 32) | (unsigned long long)(~idx);
}

/* =======================================================================
 * Kernel 1: FPS, cluster-distributed, key-only chain, coords in SMEM.
 * 8 CTAs/batch x 512 thr x 4 points. Batch coords cached in 192KB SMEM
 * (SoA) so the winner's xyz is 3 broadcast LDS after the index reduce.
 * Per iter: packed exact dist update -> local argmax -> warp xor-reduce
 * (u64 key) -> leaders STS -> one sync -> warp0 reduces 16 keys via shfl,
 * lanes 0..7 push CTA key to rank=lane + remote mbarrier arrive (double
 * buffered) -> all threads mbar wait -> reduce 8 slot keys -> idx ->
 * coords from SMEM.
 * ===================================================================== */
__global__ void __launch_bounds__(FPS_T, 1) __cluster_dims__(CLU, 1, 1)
fps_kernel(const float* __restrict__ p, float* __restrict__ out)
{
    extern __shared__ float scoord[];                /* sx|sy|sz, 3*NN */
    float* __restrict__ sx = scoord;
    float* __restrict__ sy = scoord + NN;
    float* __restrict__ sz = scoord + 2 * NN;
    __shared__ unsigned long long skeys[16];
    __shared__ unsigned long long slots[2][CLU];     /* key only */
    __shared__ alignas(8) unsigned long long mbar[2];

    const int t = threadIdx.x;
    const int r = blockIdx.x & (CLU - 1);
    const int b = blockIdx.x / CLU;
    const int w = t >> 5, lane = t & 31;
    const unsigned nbase = (unsigned)(r * (NN / CLU) + t);   /* +k*512 */
    const float* __restrict__ pb = p + (size_t)b * NN * 3;
    float* __restrict__ centerP = out + CP_OFF;

    if (t == 0) { mbar_init(smem_u32(&mbar[0]), CLU); mbar_init(smem_u32(&mbar[1]), CLU); }

    /* fill SoA coord cache: coalesced LDG.32, scattered STS */
    for (int i = t; i < NN * 3; i += FPS_T) {
        const float v = pb[i];
        const int pt = i / 3, c = i - pt * 3;
        if (c == 0) sx[pt] = v; else if (c == 1) sy[pt] = v; else sz[pt] = v;
    }

    /* coords of my 4 points in registers: pairs (k0,k1), (k2,k3) */
    unsigned long long X[2], Y[2], Z[2];
#pragma unroll
    for (int q = 0; q < 2; q++) {
        int n0 = (int)nbase + (2 * q) * FPS_T;
        int n1 = n0 + FPS_T;
        X[q] = pk2(pb[n0 * 3 + 0], pb[n1 * 3 + 0]);
        Y[q] = pk2(pb[n0 * 3 + 1], pb[n1 * 3 + 1]);
        Z[q] = pk2(pb[n0 * 3 + 2], pb[n1 * 3 + 2]);
    }
    float d0 = 1e10f, d1 = 1e10f, d2 = 1e10f, d3 = 1e10f;

    /* remote slot/barrier addrs for pusher role (warp0 lanes 0..7) */
    uint32_t rslot[2], rbar[2];
#pragma unroll
    for (int q = 0; q < 2; q++) {
        rslot[q] = mapa_u32(smem_u32(&slots[q][r]), (uint32_t)(lane & 7));
        rbar[q]  = mapa_u32(smem_u32(&mbar[q]),     (uint32_t)(lane & 7));
    }

    float cx = pb[0], cy = pb[1], cz = pb[2];        /* center 0 = point 0 */
    if (r == 0 && t == 0) {
        g_fpsidx[b * MM + 0] = 0;
        centerP[(b * MM + 0) * 3 + 0] = cx;
        centerP[(b * MM + 0) * 3 + 1] = cy;
        centerP[(b * MM + 0) * 3 + 2] = cz;
    }

    __syncthreads();   /* SoA cache complete */
    /* mbarrier init must be cluster-visible before first remote arrive */
    asm volatile("barrier.cluster.arrive.aligned;" ::: "memory");
    asm volatile("barrier.cluster.wait.aligned;" ::: "memory");

    for (int m = 1; m < MM; m++) {
        const unsigned long long ncx = pk2(-cx, -cx);
        const unsigned long long ncy = pk2(-cy, -cy);
        const unsigned long long ncz = pk2(-cz, -cz);

        /* exact packed distance update: ((dx*dx+dy*dy)+dz*dz), then min */
        {
            unsigned long long dx = add2(X[0], ncx);
            unsigned long long dy = add2(Y[0], ncy);
            unsigned long long dz = add2(Z[0], ncz);
            float2 dv = upk2(add2(add2(mul2(dx, dx), mul2(dy, dy)), mul2(dz, dz)));
            d0 = fminf(d0, dv.x); d1 = fminf(d1, dv.y);
        }
        {
            unsigned long long dx = add2(X[1], ncx);
            unsigned long long dy = add2(Y[1], ncy);
            unsigned long long dz = add2(Z[1], ncz);
            float2 dv = upk2(add2(add2(mul2(dx, dx), mul2(dy, dy)), mul2(dz, dz)));
            d2 = fminf(d2, dv.x); d3 = fminf(d3, dv.y);
        }

        /* thread-local argmax over 4 (ascending k keeps first-max) */
        float bv = d0; int bk = 0;
        if (d1 > bv) { bv = d1; bk = 1; }
        if (d2 > bv) { bv = d2; bk = 2; }
        if (d3 > bv) { bv = d3; bk = 3; }
        unsigned long long key = mkkey(bv, nbase + (unsigned)bk * FPS_T);

        /* warp xor-reduce on the key */
#pragma unroll
        for (int off = 16; off > 0; off >>= 1) {
            unsigned long long o = __shfl_xor_sync(0xffffffffu, key, off);
            if (o > key) key = o;
        }
        if (lane == 0) skeys[w] = key;
        __syncthreads();

        const int q = m & 1;
        if (w == 0) {
            /* 16 warp keys live in lanes: lane L reads skeys[L&15] */
            unsigned long long k2 = skeys[lane & 15];
#pragma unroll
            for (int off = 8; off > 0; off >>= 1) {
                unsigned long long o = __shfl_xor_sync(0xffffffffu, k2, off);
                if (o > k2) k2 = o;
            }
            if (lane < CLU) {          /* 8 lanes push in parallel */
                st_clu64(rslot[q], k2);
                mbar_arrive_remote(rbar[q]);
            }
        }

        /* wait for all 8 ranks (parity by per-buffer use count) */
        const uint32_t parity = (uint32_t)(((m >> 1) + (m & 1) + 1) & 1);
        mbar_wait(smem_u32(&mbar[q]), parity);

        /* reduce 8 slot keys */
        unsigned long long wkey = slots[q][0];
#pragma unroll
        for (int j = 1; j < 8; j++) {
            unsigned long long o = slots[q][j];
            if (o > wkey) wkey = o;
        }
        const unsigned widx = ~(unsigned)(uint32_t)wkey;   /* < 16384 */

        /* winner coords from SMEM cache (bit-identical to p[widx]) */
        cx = sx[widx]; cy = sy[widx]; cz = sz[widx];

        if (r == 0 && t == 0) {
            g_fpsidx[b * MM + m] = (int)widx;
            centerP[(b * MM + m) * 3 + 0] = cx;
            centerP[(b * MM + m) * 3 + 1] = cy;
            centerP[(b * MM + m) * 3 + 2] = cz;
        }
    }

    /* drain: no CTA exits while peers' remote ops could be in flight */
    asm volatile("barrier.cluster.arrive.aligned;" ::: "memory");
    asm volatile("barrier.cluster.wait.aligned;" ::: "memory");
}

/* =======================================================================
 * Kernel 2: ball query, warp per center. 4 chunks (128 pts) per exit
 * check; ballot + prefix-popc ordered append; pad with first neighbor.
 * Also writes grouped_p (= p[nidx]-center), exact __fsub_rn.
 * ===================================================================== */
__global__ void __launch_bounds__(256)
ballquery_kernel(const float* __restrict__ p, float* __restrict__ out)
{
    __shared__ int sidx[8][NS];
    const int lane = threadIdx.x & 31;
    const int wloc = threadIdx.x >> 5;
    const int gw   = blockIdx.x * 8 + wloc;
    const int b = gw >> 8;
    const int m = gw & (MM - 1);

    const float* __restrict__ centerP = out + CP_OFF;
    const float cx = centerP[(b * MM + m) * 3 + 0];
    const float cy = centerP[(b * MM + m) * 3 + 1];
    const float cz = centerP[(b * MM + m) * 3 + 2];
    const float R2 = 0.01f;

    const float* __restrict__ pb = p + (size_t)b * NN * 3;

    int cnt = 0;
    for (int base = 0; base < NN && cnt < NS; base += 128) {
        unsigned msk[4];
#pragma unroll
        for (int j = 0; j < 4; j++) {
            const int n = base + j * 32 + lane;
            const float dx = __fsub_rn(cx, pb[n * 3 + 0]);
            const float dy = __fsub_rn(cy, pb[n * 3 + 1]);
            const float dz = __fsub_rn(cz, pb[n * 3 + 2]);
            const float d2 = __fadd_rn(__fadd_rn(__fmul_rn(dx, dx), __fmul_rn(dy, dy)),
                                       __fmul_rn(dz, dz));
            msk[j] = __ballot_sync(0xffffffffu, d2 < R2);
        }
#pragma unroll
        for (int j = 0; j < 4; j++) {
            const int n = base + j * 32 + lane;
            const bool in = (msk[j] >> lane) & 1u;
            const int pos = cnt + __popc(msk[j] & ((1u << lane) - 1u));
            if (in && pos < NS) sidx[wloc][pos] = n;
            cnt += __popc(msk[j]);
        }
    }
    if (cnt > NS) cnt = NS;
    __syncwarp();

    const int first = sidx[wloc][0];
    const int myidx = (lane < cnt) ? sidx[wloc][lane] : first;
    g_nidx[(b * MM + m) * NS + lane] = myidx;

    const float gx = pb[myidx * 3 + 0];
    const float gy = pb[myidx * 3 + 1];
    const float gz = pb[myidx * 3 + 2];
    float* __restrict__ gp = out + GP_OFF;
    gp[((size_t)(b * 3 + 0) * MM + m) * NS + lane] = __fsub_rn(gx, cx);
    gp[((size_t)(b * 3 + 1) * MM + m) * NS + lane] = __fsub_rn(gy, cy);
    gp[((size_t)(b * 3 + 2) * MM + m) * NS + lane] = __fsub_rn(gz, cz);
}

/* =======================================================================
 * Kernel 3: feature gathers. Block per (b,m); 8 channels x 32 samples
 * per step, 16 steps over C=128. Coalesced fj writes.
 * ===================================================================== */
__global__ void __launch_bounds__(256)
gather_kernel(const float* __restrict__ x, float* __restrict__ out)
{
    __shared__ int sidx[NS];
    __shared__ int scidx;
    const int bm = blockIdx.x;
    const int b  = bm >> 8;
    const int m  = bm & (MM - 1);
    const int tid = threadIdx.x;

    if (tid < NS) sidx[tid] = g_nidx[bm * NS + tid];
    if (tid == 0) scidx = g_fpsidx[bm];
    __syncthreads();

    const int s  = tid & 31;
    const int cl = tid >> 5;
    const float* __restrict__ xb = x + (size_t)b * CC * NN;
    float* __restrict__ fj = out + FJ_OFF;
    float* __restrict__ cxo = out + CX_OFF;
    const int ci = scidx;
    const int myn = sidx[s];

#pragma unroll
    for (int rr = 0; rr < 16; rr++) {
        const int c = rr * 8 + cl;
        const float* __restrict__ row = xb + (size_t)c * NN;
        fj[(((size_t)(b * CC + c) * MM + m) << 5) + s] = __ldg(row + myn);
        if (s == 0)
            cxo[(size_t)(b * CC + c) * MM + m] = __ldg(row + ci);
    }
}

/* ======================================================================= */
extern "C" void kernel_launch(void* const* d_in, const int* in_sizes, int n_in,
                              void* d_out, int out_size)
{
    const float* p = (const float*)d_in[0];
    const float* x = (const float*)d_in[1];
    if (n_in >= 2 && in_sizes[0] > in_sizes[1]) {
        p = (const float*)d_in[1];
        x = (const float*)d_in[0];
    }
    float* out = (float*)d_out;

    static int configured = 0;
    if (!configured) {
        cudaFuncSetAttribute(fps_kernel,
                             cudaFuncAttributeMaxDynamicSharedMemorySize,
                             NN * 3 * (int)sizeof(float));
        configured = 1;
    }

    fps_kernel<<<BB * CLU, FPS_T, NN * 3 * sizeof(float)>>>(p, out);
    ballquery_kernel<<<(BB * MM) / 8, 256>>>(p, out);
    gather_kernel<<<BB * MM, 256>>>(x, out);
}

// round 5
// speedup vs baseline: 1.1840x; 1.0309x over previous
#include <cuda_runtime.h>
#include <cstdint>
#include <cstddef>

#define BB 8
#define NN 16384
#define MM 256
#define CC 128
#define NS 32
#define FPS_T 512
#define CLU 8                 /* cluster size: CTAs per batch */

/* output layout (concatenated, float32) */
#define GP_OFF 0                      /* grouped_p [8,3,256,32]  */
#define CP_OFF 196608                 /* center_p  [8,256,3]     */
#define FJ_OFF 202752                 /* fj        [8,128,256,32]*/
#define CX_OFF 8591360                /* center_x  [8,128,256,1] */

__device__ int g_fpsidx[BB * MM];
__device__ int g_nidx[BB * MM * NS];

/* ---------- exact-rounding f32x2 helpers (no FMA contraction) ---------- */
__device__ __forceinline__ unsigned long long pk2(float lo, float hi) {
    unsigned long long r;
    asm("mov.b64 %0, {%1,%2};" : "=l"(r) : "f"(lo), "f"(hi));
    return r;
}
__device__ __forceinline__ float2 upk2(unsigned long long v) {
    float2 r;
    asm("mov.b64 {%0,%1}, %2;" : "=f"(r.x), "=f"(r.y) : "l"(v));
    return r;
}
__device__ __forceinline__ unsigned long long add2(unsigned long long a, unsigned long long b) {
    unsigned long long r;
    asm("add.rn.f32x2 %0, %1, %2;" : "=l"(r) : "l"(a), "l"(b));
    return r;
}
__device__ __forceinline__ unsigned long long mul2(unsigned long long a, unsigned long long b) {
    unsigned long long r;
    asm("mul.rn.f32x2 %0, %1, %2;" : "=l"(r) : "l"(a), "l"(b));
    return r;
}
__device__ __forceinline__ uint32_t smem_u32(const void* p) {
    uint32_t a;
    asm("{ .reg .u64 t; cvta.to.shared.u64 t, %1; cvt.u32.u64 %0, t; }"
        : "=r"(a) : "l"(p));
    return a;
}
__device__ __forceinline__ uint32_t mapa_u32(uint32_t local, uint32_t rank) {
    uint32_t r;
    asm("mapa.shared::cluster.u32 %0, %1, %2;" : "=r"(r) : "r"(local), "r"(rank));
    return r;
}
__device__ __forceinline__ void st_clu64(uint32_t addr, unsigned long long v) {
    asm volatile("st.shared::cluster.u64 [%0], %1;" :: "r"(addr), "l"(v) : "memory");
}
__device__ __forceinline__ void mbar_init(uint32_t addr, uint32_t count) {
    asm volatile("mbarrier.init.shared.b64 [%0], %1;" :: "r"(addr), "r"(count) : "memory");
}
__device__ __forceinline__ void mbar_arrive_remote(uint32_t addr) {
    asm volatile("mbarrier.arrive.release.cluster.shared::cluster.b64 _, [%0];"
                 :: "r"(addr) : "memory");
}
__device__ __forceinline__ void mbar_wait(uint32_t addr, uint32_t parity) {
    uint32_t done;
    asm volatile(
        "{\n\t.reg .pred p;\n\t"
        "mbarrier.try_wait.parity.acquire.cluster.shared::cta.b64 p, [%1], %2;\n\t"
        "selp.b32 %0, 1, 0, p;\n\t}"
        : "=r"(done) : "r"(addr), "r"(parity) : "memory");
    if (!done) {
        asm volatile(
            "{\n\t.reg .pred P1;\n\t"
            "WAIT_LOOP_%=:\n\t"
            "mbarrier.try_wait.parity.acquire.cluster.shared::cta.b64 P1, [%0], %1, 0x989680;\n\t"
            "@P1 bra.uni WAIT_DONE_%=;\n\t"
            "bra.uni WAIT_LOOP_%=;\n\t"
            "WAIT_DONE_%=:\n\t}"
            :: "r"(addr), "r"(parity) : "memory");
    }
}

/* =======================================================================
 * Kernel 1: FPS, cluster-distributed, REDUX argmax, key-only chain.
 * Ownership is index-contiguous (thread t owns points r*2048+4t+{0..3}),
 * so (max value, lowest lane / warp / rank) == first-max index — letting
 * every reduce level use REDUX.MAX.U32 + ballot + ffs instead of u64
 * shuffle trees. Coords served from a 192KB SMEM SoA cache. Cluster
 * handoff: 8 lanes of warp0 push the CTA key u64 to all ranks' slots +
 * remote mbarrier arrive (double-buffered); all threads acquire-wait,
 * reduce 8 slot keys, fetch winner coords by LDS.
 * ===================================================================== */
__global__ void __launch_bounds__(FPS_T, 1) __cluster_dims__(CLU, 1, 1)
fps_kernel(const float* __restrict__ p, float* __restrict__ out)
{
    extern __shared__ float scoord[];                /* sx|sy|sz, 3*NN */
    float* __restrict__ sx = scoord;
    float* __restrict__ sy = scoord + NN;
    float* __restrict__ sz = scoord + 2 * NN;
    __shared__ unsigned sval[16];
    __shared__ unsigned sidx16[16];
    __shared__ unsigned long long slots[2][CLU];     /* key only */
    __shared__ alignas(8) unsigned long long mbar[2];

    const int t = threadIdx.x;
    const int r = blockIdx.x & (CLU - 1);
    const int b = blockIdx.x / CLU;
    const int w = t >> 5, lane = t & 31;
    const unsigned g0 = (unsigned)(r * (NN / CLU) + 4 * t);  /* my 4 pts */
    const float* __restrict__ pb = p + (size_t)b * NN * 3;
    float* __restrict__ centerP = out + CP_OFF;

    if (t == 0) { mbar_init(smem_u32(&mbar[0]), CLU); mbar_init(smem_u32(&mbar[1]), CLU); }

    /* fill SoA coord cache */
    for (int i = t; i < NN * 3; i += FPS_T) {
        const float v = pb[i];
        const int pt = i / 3, c = i - pt * 3;
        if (c == 0) sx[pt] = v; else if (c == 1) sy[pt] = v; else sz[pt] = v;
    }

    /* my 4 contiguous points -> 2 f32x2 pairs per axis (3x float4 load) */
    const float4 v0 = *(const float4*)(pb + (size_t)g0 * 3);
    const float4 v1 = *(const float4*)(pb + (size_t)g0 * 3 + 4);
    const float4 v2 = *(const float4*)(pb + (size_t)g0 * 3 + 8);
    unsigned long long X[2], Y[2], Z[2];
    X[0] = pk2(v0.x, v0.w); Y[0] = pk2(v0.y, v1.x); Z[0] = pk2(v0.z, v1.y);
    X[1] = pk2(v1.z, v2.y); Y[1] = pk2(v1.w, v2.z); Z[1] = pk2(v2.x, v2.w);
    float d0 = 1e10f, d1 = 1e10f, d2 = 1e10f, d3 = 1e10f;

    /* remote slot/barrier addrs for pusher role (warp0 lanes 0..7) */
    uint32_t rslot[2], rbar[2];
#pragma unroll
    for (int q = 0; q < 2; q++) {
        rslot[q] = mapa_u32(smem_u32(&slots[q][r]), (uint32_t)(lane & 7));
        rbar[q]  = mapa_u32(smem_u32(&mbar[q]),     (uint32_t)(lane & 7));
    }

    float cx = pb[0], cy = pb[1], cz = pb[2];        /* center 0 = point 0 */
    if (r == 0 && t == 0) {
        g_fpsidx[b * MM + 0] = 0;
        centerP[(b * MM + 0) * 3 + 0] = cx;
        centerP[(b * MM + 0) * 3 + 1] = cy;
        centerP[(b * MM + 0) * 3 + 2] = cz;
    }

    __syncthreads();   /* SoA cache complete */
    asm volatile("barrier.cluster.arrive.aligned;" ::: "memory");
    asm volatile("barrier.cluster.wait.aligned;" ::: "memory");

    for (int m = 1; m < MM; m++) {
        const unsigned long long ncx = pk2(-cx, -cx);
        const unsigned long long ncy = pk2(-cy, -cy);
        const unsigned long long ncz = pk2(-cz, -cz);

        /* exact packed distance update: ((dx*dx+dy*dy)+dz*dz), then min */
        {
            unsigned long long dx = add2(X[0], ncx);
            unsigned long long dy = add2(Y[0], ncy);
            unsigned long long dz = add2(Z[0], ncz);
            float2 dv = upk2(add2(add2(mul2(dx, dx), mul2(dy, dy)), mul2(dz, dz)));
            d0 = fminf(d0, dv.x); d1 = fminf(d1, dv.y);
        }
        {
            unsigned long long dx = add2(X[1], ncx);
            unsigned long long dy = add2(Y[1], ncy);
            unsigned long long dz = add2(Z[1], ncz);
            float2 dv = upk2(add2(add2(mul2(dx, dx), mul2(dy, dy)), mul2(dz, dz)));
            d2 = fminf(d2, dv.x); d3 = fminf(d3, dv.y);
        }

        /* local argmax over 4 contiguous (ascending keeps first-max) */
        float bv = d0; unsigned bk = 0;
        if (d1 > bv) { bv = d1; bk = 1; }
        if (d2 > bv) { bv = d2; bk = 2; }
        if (d3 > bv) { bv = d3; bk = 3; }
        const unsigned bi = g0 + bk;

        /* warp argmax: REDUX on f32-as-u32 (d>=0), lowest lane on ties */
        const unsigned vb   = __float_as_uint(bv);
        const unsigned wmax = __reduce_max_sync(0xffffffffu, vb);
        const unsigned tied = __ballot_sync(0xffffffffu, vb == wmax);
        const int      src  = __ffs(tied) - 1;
        const unsigned widx_w = __shfl_sync(0xffffffffu, bi, src);
        if (lane == 0) { sval[w] = wmax; sidx16[w] = widx_w; }

        /* split barrier: only warp0 blocks on the block reduce */
        const int q = m & 1;
        if (w != 0) {
            asm volatile("bar.arrive 1, 512;" ::: "memory");
        } else {
            asm volatile("bar.sync 1, 512;" ::: "memory");
            /* block argmax over 16 warp winners (lanes 16..31 mirror) */
            const unsigned v16  = sval[lane & 15];
            const unsigned bmax = __reduce_max_sync(0xffffffffu, v16);
            const unsigned bt   = __ballot_sync(0xffffffffu, v16 == bmax);
            const int      bs   = __ffs(bt) - 1;        /* lowest warp id */
            const unsigned bidx = sidx16[bs & 15];
            const unsigned long long key =
                ((unsigned long long)bmax << 32) | (unsigned long long)(~bidx);
            if (lane < CLU) {          /* 8 lanes push in parallel */
                st_clu64(rslot[q], key);
                mbar_arrive_remote(rbar[q]);
            }
        }

        /* wait for all 8 ranks (parity by per-buffer use count) */
        const uint32_t parity = (uint32_t)(((m >> 1) + (m & 1) + 1) & 1);
        mbar_wait(smem_u32(&mbar[q]), parity);

        /* reduce 8 slot keys (tree), winner idx from ~low32 */
        unsigned long long k0 = slots[q][0], k1 = slots[q][1];
        unsigned long long k2 = slots[q][2], k3 = slots[q][3];
        unsigned long long k4 = slots[q][4], k5 = slots[q][5];
        unsigned long long k6 = slots[q][6], k7 = slots[q][7];
        if (k1 > k0) k0 = k1;  if (k3 > k2) k2 = k3;
        if (k5 > k4) k4 = k5;  if (k7 > k6) k6 = k7;
        if (k2 > k0) k0 = k2;  if (k6 > k4) k4 = k6;
        if (k4 > k0) k0 = k4;
        const unsigned widx = ~(unsigned)(uint32_t)k0;   /* < 16384 */

        /* winner coords from SMEM cache (bit-identical to p[widx]) */
        cx = sx[widx]; cy = sy[widx]; cz = sz[widx];

        if (r == 0 && t == 0) {
            g_fpsidx[b * MM + m] = (int)widx;
            centerP[(b * MM + m) * 3 + 0] = cx;
            centerP[(b * MM + m) * 3 + 1] = cy;
            centerP[(b * MM + m) * 3 + 2] = cz;
        }
    }

    /* drain: no CTA exits while peers' remote ops could be in flight */
    asm volatile("barrier.cluster.arrive.aligned;" ::: "memory");
    asm volatile("barrier.cluster.wait.aligned;" ::: "memory");
}

/* =======================================================================
 * Kernel 2: ball query, warp per center. 4 chunks (128 pts) per exit
 * check; ballot + prefix-popc ordered append; pad with first neighbor.
 * Also writes grouped_p (= p[nidx]-center), exact __fsub_rn.
 * ===================================================================== */
__global__ void __launch_bounds__(256)
ballquery_kernel(const float* __restrict__ p, float* __restrict__ out)
{
    __shared__ int sidx[8][NS];
    const int lane = threadIdx.x & 31;
    const int wloc = threadIdx.x >> 5;
    const int gw   = blockIdx.x * 8 + wloc;
    const int b = gw >> 8;
    const int m = gw & (MM - 1);

    const float* __restrict__ centerP = out + CP_OFF;
    const float cx = centerP[(b * MM + m) * 3 + 0];
    const float cy = centerP[(b * MM + m) * 3 + 1];
    const float cz = centerP[(b * MM + m) * 3 + 2];
    const float R2 = 0.01f;

    const float* __restrict__ pb = p + (size_t)b * NN * 3;

    int cnt = 0;
    for (int base = 0; base < NN && cnt < NS; base += 128) {
        unsigned msk[4];
#pragma unroll
        for (int j = 0; j < 4; j++) {
            const int n = base + j * 32 + lane;
            const float dx = __fsub_rn(cx, pb[n * 3 + 0]);
            const float dy = __fsub_rn(cy, pb[n * 3 + 1]);
            const float dz = __fsub_rn(cz, pb[n * 3 + 2]);
            const float d2 = __fadd_rn(__fadd_rn(__fmul_rn(dx, dx), __fmul_rn(dy, dy)),
                                       __fmul_rn(dz, dz));
            msk[j] = __ballot_sync(0xffffffffu, d2 < R2);
        }
#pragma unroll
        for (int j = 0; j < 4; j++) {
            const int n = base + j * 32 + lane;
            const bool in = (msk[j] >> lane) & 1u;
            const int pos = cnt + __popc(msk[j] & ((1u << lane) - 1u));
            if (in && pos < NS) sidx[wloc][pos] = n;
            cnt += __popc(msk[j]);
        }
    }
    if (cnt > NS) cnt = NS;
    __syncwarp();

    const int first = sidx[wloc][0];
    const int myidx = (lane < cnt) ? sidx[wloc][lane] : first;
    g_nidx[(b * MM + m) * NS + lane] = myidx;

    const float gx = pb[myidx * 3 + 0];
    const float gy = pb[myidx * 3 + 1];
    const float gz = pb[myidx * 3 + 2];
    float* __restrict__ gp = out + GP_OFF;
    gp[((size_t)(b * 3 + 0) * MM + m) * NS + lane] = __fsub_rn(gx, cx);
    gp[((size_t)(b * 3 + 1) * MM + m) * NS + lane] = __fsub_rn(gy, cy);
    gp[((size_t)(b * 3 + 2) * MM + m) * NS + lane] = __fsub_rn(gz, cz);
}

/* =======================================================================
 * Kernel 3: feature gathers. Block per (b,m); 8 channels x 32 samples
 * per step, 16 steps over C=128. Coalesced fj writes.
 * ===================================================================== */
__global__ void __launch_bounds__(256)
gather_kernel(const float* __restrict__ x, float* __restrict__ out)
{
    __shared__ int sidx[NS];
    __shared__ int scidx;
    const int bm = blockIdx.x;
    const int b  = bm >> 8;
    const int m  = bm & (MM - 1);
    const int tid = threadIdx.x;

    if (tid < NS) sidx[tid] = g_nidx[bm * NS + tid];
    if (tid == 0) scidx = g_fpsidx[bm];
    __syncthreads();

    const int s  = tid & 31;
    const int cl = tid >> 5;
    const float* __restrict__ xb = x + (size_t)b * CC * NN;
    float* __restrict__ fj = out + FJ_OFF;
    float* __restrict__ cxo = out + CX_OFF;
    const int ci = scidx;
    const int myn = sidx[s];

#pragma unroll
    for (int rr = 0; rr < 16; rr++) {
        const int c = rr * 8 + cl;
        const float* __restrict__ row = xb + (size_t)c * NN;
        fj[(((size_t)(b * CC + c) * MM + m) << 5) + s] = __ldg(row + myn);
        if (s == 0)
            cxo[(size_t)(b * CC + c) * MM + m] = __ldg(row + ci);
    }
}

/* ======================================================================= */
extern "C" void kernel_launch(void* const* d_in, const int* in_sizes, int n_in,
                              void* d_out, int out_size)
{
    const float* p = (const float*)d_in[0];
    const float* x = (const float*)d_in[1];
    if (n_in >= 2 && in_sizes[0] > in_sizes[1]) {
        p = (const float*)d_in[1];
        x = (const float*)d_in[0];
    }
    float* out = (float*)d_out;

    static int configured = 0;
    if (!configured) {
        cudaFuncSetAttribute(fps_kernel,
                             cudaFuncAttributeMaxDynamicSharedMemorySize,
                             NN * 3 * (int)sizeof(float));
        configured = 1;
    }

    fps_kernel<<<BB * CLU, FPS_T, NN * 3 * sizeof(float)>>>(p, out);
    ballquery_kernel<<<(BB * MM) / 8, 256>>>(p, out);
    gather_kernel<<<BB * MM, 256>>>(x, out);
}

// round 6
// speedup vs baseline: 1.2322x; 1.0407x over previous
#include <cuda_runtime.h>
#include <cstdint>
#include <cstddef>

#define BB 8
#define NN 16384
#define MM 256
#define CC 128
#define NS 32
#define FPS_T 512
#define CLU 8                 /* cluster size: CTAs per batch */
#define NBUF 8                /* slot ring depth */

/* output layout (concatenated, float32) */
#define GP_OFF 0                      /* grouped_p [8,3,256,32]  */
#define CP_OFF 196608                 /* center_p  [8,256,3]     */
#define FJ_OFF 202752                 /* fj        [8,128,256,32]*/
#define CX_OFF 8591360                /* center_x  [8,128,256,1] */

__device__ int g_fpsidx[BB * MM];

/* ---------- exact-rounding f32x2 helpers (no FMA contraction) ---------- */
__device__ __forceinline__ unsigned long long pk2(float lo, float hi) {
    unsigned long long r;
    asm("mov.b64 %0, {%1,%2};" : "=l"(r) : "f"(lo), "f"(hi));
    return r;
}
__device__ __forceinline__ float2 upk2(unsigned long long v) {
    float2 r;
    asm("mov.b64 {%0,%1}, %2;" : "=f"(r.x), "=f"(r.y) : "l"(v));
    return r;
}
__device__ __forceinline__ unsigned long long add2(unsigned long long a, unsigned long long b) {
    unsigned long long r;
    asm("add.rn.f32x2 %0, %1, %2;" : "=l"(r) : "l"(a), "l"(b));
    return r;
}
__device__ __forceinline__ unsigned long long mul2(unsigned long long a, unsigned long long b) {
    unsigned long long r;
    asm("mul.rn.f32x2 %0, %1, %2;" : "=l"(r) : "l"(a), "l"(b));
    return r;
}
__device__ __forceinline__ uint32_t smem_u32(const void* p) {
    uint32_t a;
    asm("{ .reg .u64 t; cvta.to.shared.u64 t, %1; cvt.u32.u64 %0, t; }"
        : "=r"(a) : "l"(p));
    return a;
}
__device__ __forceinline__ uint32_t mapa_u32(uint32_t local, uint32_t rank) {
    uint32_t r;
    asm("mapa.shared::cluster.u32 %0, %1, %2;" : "=r"(r) : "r"(local), "r"(rank));
    return r;
}
/* one-shot flag-in-data remote store (relaxed atomic u64, cluster scope) */
__device__ __forceinline__ void st_relaxed_clu64(uint32_t addr, unsigned long long v) {
    asm volatile("st.relaxed.cluster.shared::cluster.u64 [%0], %1;"
                 :: "r"(addr), "l"(v) : "memory");
}
__device__ __forceinline__ unsigned long long ld_relaxed_clu64(uint32_t addr) {
    unsigned long long v;
    asm volatile("ld.relaxed.cluster.shared::cta.u64 %0, [%1];"
                 : "=l"(v) : "r"(addr) : "memory");
    return v;
}

/* =======================================================================
 * Kernel 1: FPS, cluster-distributed, REDUX argmax, flag-in-data handoff.
 * Thread t of rank r owns points r*2048+4t+{0..3} (index-contiguous), so
 * (max val, lowest lane/warp/rank) == first-max index at every level.
 * Per iter: packed exact dist update -> local argmax -> warp REDUX ->
 * leaders STS -> split bar -> warp0 block REDUX -> lanes 0..7 push key
 * u64 (val | tag | ~idx) straight to all ranks' slot ring (NO mbarrier)
 * -> all threads spin on their 8 local slots until tags match -> reduce
 * keys -> coords from 192KB SMEM SoA cache.
 * ===================================================================== */
__global__ void __launch_bounds__(FPS_T, 1) __cluster_dims__(CLU, 1, 1)
fps_kernel(const float* __restrict__ p, float* __restrict__ out)
{
    extern __shared__ float scoord[];                /* sx|sy|sz, 3*NN */
    float* __restrict__ sx = scoord;
    float* __restrict__ sy = scoord + NN;
    float* __restrict__ sz = scoord + 2 * NN;
    __shared__ unsigned sval[16];
    __shared__ unsigned sidx16[16];
    __shared__ alignas(8) unsigned long long slots[NBUF][CLU];

    const int t = threadIdx.x;
    const int r = blockIdx.x & (CLU - 1);
    const int b = blockIdx.x / CLU;
    const int w = t >> 5, lane = t & 31;
    const unsigned g0 = (unsigned)(r * (NN / CLU) + 4 * t);  /* my 4 pts */
    const float* __restrict__ pb = p + (size_t)b * NN * 3;
    float* __restrict__ centerP = out + CP_OFF;

    /* zero the slot ring (tag 0 never matches m=1..255) */
    if (t < NBUF * CLU) slots[t >> 3][t & 7] = 0ull;

    /* fill SoA coord cache */
    for (int i = t; i < NN * 3; i += FPS_T) {
        const float v = pb[i];
        const int pt = i / 3, c = i - pt * 3;
        if (c == 0) sx[pt] = v; else if (c == 1) sy[pt] = v; else sz[pt] = v;
    }

    /* my 4 contiguous points -> 2 f32x2 pairs per axis (3x float4 load) */
    const float4 v0 = *(const float4*)(pb + (size_t)g0 * 3);
    const float4 v1 = *(const float4*)(pb + (size_t)g0 * 3 + 4);
    const float4 v2 = *(const float4*)(pb + (size_t)g0 * 3 + 8);
    unsigned long long X[2], Y[2], Z[2];
    X[0] = pk2(v0.x, v0.w); Y[0] = pk2(v0.y, v1.x); Z[0] = pk2(v0.z, v1.y);
    X[1] = pk2(v1.z, v2.y); Y[1] = pk2(v1.w, v2.z); Z[1] = pk2(v2.x, v2.w);
    float d0 = 1e10f, d1 = 1e10f, d2 = 1e10f, d3 = 1e10f;

    /* remote slot addrs for pusher role (warp0 lanes 0..7), per buffer */
    uint32_t rslot[NBUF];
#pragma unroll
    for (int q = 0; q < NBUF; q++)
        rslot[q] = mapa_u32(smem_u32(&slots[q][r]), (uint32_t)(lane & 7));
    const uint32_t lslot0 = smem_u32(&slots[0][0]);

    float cx = pb[0], cy = pb[1], cz = pb[2];        /* center 0 = point 0 */
    if (r == 0 && t == 0) {
        g_fpsidx[b * MM + 0] = 0;
        centerP[(b * MM + 0) * 3 + 0] = cx;
        centerP[(b * MM + 0) * 3 + 1] = cy;
        centerP[(b * MM + 0) * 3 + 2] = cz;
    }

    __syncthreads();   /* SoA cache + slot init complete */
    /* slot init must be cluster-visible before any remote push */
    asm volatile("barrier.cluster.arrive.aligned;" ::: "memory");
    asm volatile("barrier.cluster.wait.aligned;" ::: "memory");

    for (int m = 1; m < MM; m++) {
        const unsigned long long ncx = pk2(-cx, -cx);
        const unsigned long long ncy = pk2(-cy, -cy);
        const unsigned long long ncz = pk2(-cz, -cz);

        /* exact packed distance update: ((dx*dx+dy*dy)+dz*dz), then min */
        {
            unsigned long long dx = add2(X[0], ncx);
            unsigned long long dy = add2(Y[0], ncy);
            unsigned long long dz = add2(Z[0], ncz);
            float2 dv = upk2(add2(add2(mul2(dx, dx), mul2(dy, dy)), mul2(dz, dz)));
            d0 = fminf(d0, dv.x); d1 = fminf(d1, dv.y);
        }
        {
            unsigned long long dx = add2(X[1], ncx);
            unsigned long long dy = add2(Y[1], ncy);
            unsigned long long dz = add2(Z[1], ncz);
            float2 dv = upk2(add2(add2(mul2(dx, dx), mul2(dy, dy)), mul2(dz, dz)));
            d2 = fminf(d2, dv.x); d3 = fminf(d3, dv.y);
        }

        /* local argmax over 4 contiguous (ascending keeps first-max) */
        float bv = d0; unsigned bk = 0;
        if (d1 > bv) { bv = d1; bk = 1; }
        if (d2 > bv) { bv = d2; bk = 2; }
        if (d3 > bv) { bv = d3; bk = 3; }
        const unsigned bi = g0 + bk;

        /* warp argmax: REDUX on f32-as-u32 (d>=0), lowest lane on ties */
        const unsigned vb   = __float_as_uint(bv);
        const unsigned wmax = __reduce_max_sync(0xffffffffu, vb);
        const unsigned tied = __ballot_sync(0xffffffffu, vb == wmax);
        const int      src  = __ffs(tied) - 1;
        const unsigned widx_w = __shfl_sync(0xffffffffu, bi, src);
        if (lane == 0) { sval[w] = wmax; sidx16[w] = widx_w; }

        const int q = m & (NBUF - 1);
        const unsigned tag = (unsigned)m & 0xFFu;

        /* split barrier: only warp0 blocks on the block reduce */
        if (w != 0) {
            asm volatile("bar.arrive 1, 512;" ::: "memory");
        } else {
            asm volatile("bar.sync 1, 512;" ::: "memory");
            /* block argmax over 16 warp winners (lanes 16..31 mirror) */
            const unsigned v16  = sval[lane & 15];
            const unsigned bmax = __reduce_max_sync(0xffffffffu, v16);
            const unsigned bt   = __ballot_sync(0xffffffffu, v16 == bmax);
            const int      bs   = __ffs(bt) - 1;        /* lowest warp id */
            const unsigned bidx = sidx16[bs & 15];
            const unsigned long long key =
                ((unsigned long long)bmax << 32)
                | ((unsigned long long)tag << 14)
                | (unsigned long long)(bidx ^ 0x3FFFu);
            if (lane < CLU)            /* 8 lanes push in parallel */
                st_relaxed_clu64(rslot[q], key);
        }

        /* spin until all 8 slot tags match this iteration */
        const uint32_t base = lslot0 + (uint32_t)(q * CLU * 8);
        unsigned long long k0, k1, k2, k3, k4, k5, k6, k7;
        for (;;) {
            k0 = ld_relaxed_clu64(base);      k1 = ld_relaxed_clu64(base + 8);
            k2 = ld_relaxed_clu64(base + 16); k3 = ld_relaxed_clu64(base + 24);
            k4 = ld_relaxed_clu64(base + 32); k5 = ld_relaxed_clu64(base + 40);
            k6 = ld_relaxed_clu64(base + 48); k7 = ld_relaxed_clu64(base + 56);
            const unsigned t01 = ((unsigned)(k0 >> 14) & 0xFFu) ^ tag;
            const unsigned t1  = ((unsigned)(k1 >> 14) & 0xFFu) ^ tag;
            const unsigned t2  = ((unsigned)(k2 >> 14) & 0xFFu) ^ tag;
            const unsigned t3  = ((unsigned)(k3 >> 14) & 0xFFu) ^ tag;
            const unsigned t4  = ((unsigned)(k4 >> 14) & 0xFFu) ^ tag;
            const unsigned t5  = ((unsigned)(k5 >> 14) & 0xFFu) ^ tag;
            const unsigned t6  = ((unsigned)(k6 >> 14) & 0xFFu) ^ tag;
            const unsigned t7  = ((unsigned)(k7 >> 14) & 0xFFu) ^ tag;
            if ((t01 | t1 | t2 | t3 | t4 | t5 | t6 | t7) == 0u) break;
        }

        /* reduce 8 slot keys (tree); idx = low14 ^ 0x3FFF */
        if (k1 > k0) k0 = k1;  if (k3 > k2) k2 = k3;
        if (k5 > k4) k4 = k5;  if (k7 > k6) k6 = k7;
        if (k2 > k0) k0 = k2;  if (k6 > k4) k4 = k6;
        if (k4 > k0) k0 = k4;
        const unsigned widx = ((unsigned)k0 & 0x3FFFu) ^ 0x3FFFu;

        /* winner coords from SMEM cache (bit-identical to p[widx]) */
        cx = sx[widx]; cy = sy[widx]; cz = sz[widx];

        if (r == 0 && t == 0) {
            g_fpsidx[b * MM + m] = (int)widx;
            centerP[(b * MM + m) * 3 + 0] = cx;
            centerP[(b * MM + m) * 3 + 1] = cy;
            centerP[(b * MM + m) * 3 + 2] = cz;
        }
    }

    /* drain: no CTA exits while peers' remote stores could be in flight */
    asm volatile("barrier.cluster.arrive.aligned;" ::: "memory");
    asm volatile("barrier.cluster.wait.aligned;" ::: "memory");
}

/* =======================================================================
 * Kernel 2: fused ball query + gathers. One block per (b,m); warp 0 runs
 * the ordered radius scan (ballot + prefix-popc append, pad with first)
 * and writes grouped_p; then all 8 warps gather fj (+ center_x).
 * ===================================================================== */
__global__ void __launch_bounds__(256)
group_kernel(const float* __restrict__ p, const float* __restrict__ x,
             float* __restrict__ out)
{
    __shared__ int sidx[NS];
    const int bm = blockIdx.x;                 /* b*256+m */
    const int b  = bm >> 8;
    const int m  = bm & (MM - 1);
    const int tid = threadIdx.x;
    const int lane = tid & 31;
    const int w = tid >> 5;

    const float* __restrict__ pb = p + (size_t)b * NN * 3;
    const float* __restrict__ centerP = out + CP_OFF;

    if (w == 0) {
        const float cx = centerP[bm * 3 + 0];
        const float cy = centerP[bm * 3 + 1];
        const float cz = centerP[bm * 3 + 2];
        const float R2 = 0.01f;   /* == f32(0.1*0.1 in double), matches ref */

        int cnt = 0;
        for (int base = 0; base < NN && cnt < NS; base += 128) {
            unsigned msk[4];
#pragma unroll
            for (int j = 0; j < 4; j++) {
                const int n = base + j * 32 + lane;
                const float dx = __fsub_rn(cx, pb[n * 3 + 0]);
                const float dy = __fsub_rn(cy, pb[n * 3 + 1]);
                const float dz = __fsub_rn(cz, pb[n * 3 + 2]);
                const float d2 = __fadd_rn(__fadd_rn(__fmul_rn(dx, dx),
                                                     __fmul_rn(dy, dy)),
                                           __fmul_rn(dz, dz));
                msk[j] = __ballot_sync(0xffffffffu, d2 < R2);
            }
#pragma unroll
            for (int j = 0; j < 4; j++) {
                const int n = base + j * 32 + lane;
                const bool in = (msk[j] >> lane) & 1u;
                const int pos = cnt + __popc(msk[j] & ((1u << lane) - 1u));
                if (in && pos < NS) sidx[pos] = n;
                cnt += __popc(msk[j]);
            }
        }
        if (cnt > NS) cnt = NS;
        __syncwarp();

        const int first = sidx[0];             /* >=1: center itself */
        const int myidx = (lane < cnt) ? sidx[lane] : first;
        sidx[lane] = myidx;                    /* padded list for gather */

        const float gx = pb[myidx * 3 + 0];
        const float gy = pb[myidx * 3 + 1];
        const float gz = pb[myidx * 3 + 2];
        float* __restrict__ gp = out + GP_OFF;
        gp[((size_t)(b * 3 + 0) * MM + m) * NS + lane] = __fsub_rn(gx, cx);
        gp[((size_t)(b * 3 + 1) * MM + m) * NS + lane] = __fsub_rn(gy, cy);
        gp[((size_t)(b * 3 + 2) * MM + m) * NS + lane] = __fsub_rn(gz, cz);
    }
    __syncthreads();

    /* gathers: 8 channels x 32 samples per round, 16 rounds */
    const int s  = tid & 31;
    const int cl = tid >> 5;
    const float* __restrict__ xb = x + (size_t)b * CC * NN;
    float* __restrict__ fj = out + FJ_OFF;
    float* __restrict__ cxo = out + CX_OFF;
    const int ci = g_fpsidx[bm];
    const int myn = sidx[s];

#pragma unroll
    for (int rr = 0; rr < 16; rr++) {
        const int c = rr * 8 + cl;
        const float* __restrict__ row = xb + (size_t)c * NN;
        fj[(((size_t)(b * CC + c) * MM + m) << 5) + s] = __ldg(row + myn);
        if (s == 0)
            cxo[(size_t)(b * CC + c) * MM + m] = __ldg(row + ci);
    }
}

/* ======================================================================= */
extern "C" void kernel_launch(void* const* d_in, const int* in_sizes, int n_in,
                              void* d_out, int out_size)
{
    const float* p = (const float*)d_in[0];
    const float* x = (const float*)d_in[1];
    if (n_in >= 2 && in_sizes[0] > in_sizes[1]) {
        p = (const float*)d_in[1];
        x = (const float*)d_in[0];
    }
    float* out = (float*)d_out;

    static int configured = 0;
    if (!configured) {
        cudaFuncSetAttribute(fps_kernel,
                             cudaFuncAttributeMaxDynamicSharedMemorySize,
                             NN * 3 * (int)sizeof(float));
        configured = 1;
    }

    fps_kernel<<<BB * CLU, FPS_T, NN * 3 * sizeof(float)>>>(p, out);
    group_kernel<<<BB * MM, 256>>>(p, x, out);
}

// round 7
// speedup vs baseline: 1.5937x; 1.2934x over previous
#include <cuda_runtime.h>
#include <cstdint>
#include <cstddef>

#define BB 8
#define NN 16384
#define MM 256
#define CC 128
#define NS 32
#define FPS_T 512
#define CLU 8                 /* cluster size: CTAs per batch */
#define NBUF 8                /* slot ring depth */

/* output layout (concatenated, float32) */
#define GP_OFF 0                      /* grouped_p [8,3,256,32]  */
#define CP_OFF 196608                 /* center_p  [8,256,3]     */
#define FJ_OFF 202752                 /* fj        [8,128,256,32]*/
#define CX_OFF 8591360                /* center_x  [8,128,256,1] */

__device__ int g_fpsidx[BB * MM];

/* ---------- exact-rounding f32x2 helpers (no FMA contraction) ---------- */
__device__ __forceinline__ unsigned long long pk2(float lo, float hi) {
    unsigned long long r;
    asm("mov.b64 %0, {%1,%2};" : "=l"(r) : "f"(lo), "f"(hi));
    return r;
}
__device__ __forceinline__ float2 upk2(unsigned long long v) {
    float2 r;
    asm("mov.b64 {%0,%1}, %2;" : "=f"(r.x), "=f"(r.y) : "l"(v));
    return r;
}
__device__ __forceinline__ unsigned long long add2(unsigned long long a, unsigned long long b) {
    unsigned long long r;
    asm("add.rn.f32x2 %0, %1, %2;" : "=l"(r) : "l"(a), "l"(b));
    return r;
}
__device__ __forceinline__ unsigned long long mul2(unsigned long long a, unsigned long long b) {
    unsigned long long r;
    asm("mul.rn.f32x2 %0, %1, %2;" : "=l"(r) : "l"(a), "l"(b));
    return r;
}
__device__ __forceinline__ uint32_t smem_u32(const void* p) {
    uint32_t a;
    asm("{ .reg .u64 t; cvta.to.shared.u64 t, %1; cvt.u32.u64 %0, t; }"
        : "=r"(a) : "l"(p));
    return a;
}
__device__ __forceinline__ uint32_t mapa_u32(uint32_t local, uint32_t rank) {
    uint32_t r;
    asm("mapa.shared::cluster.u32 %0, %1, %2;" : "=r"(r) : "r"(local), "r"(rank));
    return r;
}
/* one-shot flag-in-data remote store (relaxed atomic u64, cluster scope) */
__device__ __forceinline__ void st_relaxed_clu64(uint32_t addr, unsigned long long v) {
    asm volatile("st.relaxed.cluster.shared::cluster.u64 [%0], %1;"
                 :: "r"(addr), "l"(v) : "memory");
}
__device__ __forceinline__ unsigned long long ld_relaxed_clu64(uint32_t addr) {
    unsigned long long v;
    asm volatile("ld.relaxed.cluster.shared::cta.u64 %0, [%1];"
                 : "=l"(v) : "r"(addr) : "memory");
    return v;
}

/* =======================================================================
 * Kernel 1: FPS (unchanged from R6 — cluster REDUX + flag-in-data).
 * ===================================================================== */
__global__ void __launch_bounds__(FPS_T, 1) __cluster_dims__(CLU, 1, 1)
fps_kernel(const float* __restrict__ p, float* __restrict__ out)
{
    extern __shared__ float scoord[];                /* sx|sy|sz, 3*NN */
    float* __restrict__ sx = scoord;
    float* __restrict__ sy = scoord + NN;
    float* __restrict__ sz = scoord + 2 * NN;
    __shared__ unsigned sval[16];
    __shared__ unsigned sidx16[16];
    __shared__ alignas(8) unsigned long long slots[NBUF][CLU];

    const int t = threadIdx.x;
    const int r = blockIdx.x & (CLU - 1);
    const int b = blockIdx.x / CLU;
    const int w = t >> 5, lane = t & 31;
    const unsigned g0 = (unsigned)(r * (NN / CLU) + 4 * t);  /* my 4 pts */
    const float* __restrict__ pb = p + (size_t)b * NN * 3;
    float* __restrict__ centerP = out + CP_OFF;

    if (t < NBUF * CLU) slots[t >> 3][t & 7] = 0ull;

    for (int i = t; i < NN * 3; i += FPS_T) {
        const float v = pb[i];
        const int pt = i / 3, c = i - pt * 3;
        if (c == 0) sx[pt] = v; else if (c == 1) sy[pt] = v; else sz[pt] = v;
    }

    const float4 v0 = *(const float4*)(pb + (size_t)g0 * 3);
    const float4 v1 = *(const float4*)(pb + (size_t)g0 * 3 + 4);
    const float4 v2 = *(const float4*)(pb + (size_t)g0 * 3 + 8);
    unsigned long long X[2], Y[2], Z[2];
    X[0] = pk2(v0.x, v0.w); Y[0] = pk2(v0.y, v1.x); Z[0] = pk2(v0.z, v1.y);
    X[1] = pk2(v1.z, v2.y); Y[1] = pk2(v1.w, v2.z); Z[1] = pk2(v2.x, v2.w);
    float d0 = 1e10f, d1 = 1e10f, d2 = 1e10f, d3 = 1e10f;

    uint32_t rslot[NBUF];
#pragma unroll
    for (int q = 0; q < NBUF; q++)
        rslot[q] = mapa_u32(smem_u32(&slots[q][r]), (uint32_t)(lane & 7));
    const uint32_t lslot0 = smem_u32(&slots[0][0]);

    float cx = pb[0], cy = pb[1], cz = pb[2];        /* center 0 = point 0 */
    if (r == 0 && t == 0) {
        g_fpsidx[b * MM + 0] = 0;
        centerP[(b * MM + 0) * 3 + 0] = cx;
        centerP[(b * MM + 0) * 3 + 1] = cy;
        centerP[(b * MM + 0) * 3 + 2] = cz;
    }

    __syncthreads();
    asm volatile("barrier.cluster.arrive.aligned;" ::: "memory");
    asm volatile("barrier.cluster.wait.aligned;" ::: "memory");

    for (int m = 1; m < MM; m++) {
        const unsigned long long ncx = pk2(-cx, -cx);
        const unsigned long long ncy = pk2(-cy, -cy);
        const unsigned long long ncz = pk2(-cz, -cz);

        {
            unsigned long long dx = add2(X[0], ncx);
            unsigned long long dy = add2(Y[0], ncy);
            unsigned long long dz = add2(Z[0], ncz);
            float2 dv = upk2(add2(add2(mul2(dx, dx), mul2(dy, dy)), mul2(dz, dz)));
            d0 = fminf(d0, dv.x); d1 = fminf(d1, dv.y);
        }
        {
            unsigned long long dx = add2(X[1], ncx);
            unsigned long long dy = add2(Y[1], ncy);
            unsigned long long dz = add2(Z[1], ncz);
            float2 dv = upk2(add2(add2(mul2(dx, dx), mul2(dy, dy)), mul2(dz, dz)));
            d2 = fminf(d2, dv.x); d3 = fminf(d3, dv.y);
        }

        float bv = d0; unsigned bk = 0;
        if (d1 > bv) { bv = d1; bk = 1; }
        if (d2 > bv) { bv = d2; bk = 2; }
        if (d3 > bv) { bv = d3; bk = 3; }
        const unsigned bi = g0 + bk;

        const unsigned vb   = __float_as_uint(bv);
        const unsigned wmax = __reduce_max_sync(0xffffffffu, vb);
        const unsigned tied = __ballot_sync(0xffffffffu, vb == wmax);
        const int      src  = __ffs(tied) - 1;
        const unsigned widx_w = __shfl_sync(0xffffffffu, bi, src);
        if (lane == 0) { sval[w] = wmax; sidx16[w] = widx_w; }

        const int q = m & (NBUF - 1);
        const unsigned tag = (unsigned)m & 0xFFu;

        if (w != 0) {
            asm volatile("bar.arrive 1, 512;" ::: "memory");
        } else {
            asm volatile("bar.sync 1, 512;" ::: "memory");
            const unsigned v16  = sval[lane & 15];
            const unsigned bmax = __reduce_max_sync(0xffffffffu, v16);
            const unsigned bt   = __ballot_sync(0xffffffffu, v16 == bmax);
            const int      bs   = __ffs(bt) - 1;
            const unsigned bidx = sidx16[bs & 15];
            const unsigned long long key =
                ((unsigned long long)bmax << 32)
                | ((unsigned long long)tag << 14)
                | (unsigned long long)(bidx ^ 0x3FFFu);
            if (lane < CLU)
                st_relaxed_clu64(rslot[q], key);
        }

        const uint32_t base = lslot0 + (uint32_t)(q * CLU * 8);
        unsigned long long k0, k1, k2, k3, k4, k5, k6, k7;
        for (;;) {
            k0 = ld_relaxed_clu64(base);      k1 = ld_relaxed_clu64(base + 8);
            k2 = ld_relaxed_clu64(base + 16); k3 = ld_relaxed_clu64(base + 24);
            k4 = ld_relaxed_clu64(base + 32); k5 = ld_relaxed_clu64(base + 40);
            k6 = ld_relaxed_clu64(base + 48); k7 = ld_relaxed_clu64(base + 56);
            const unsigned t0 = ((unsigned)(k0 >> 14) & 0xFFu) ^ tag;
            const unsigned t1 = ((unsigned)(k1 >> 14) & 0xFFu) ^ tag;
            const unsigned t2 = ((unsigned)(k2 >> 14) & 0xFFu) ^ tag;
            const unsigned t3 = ((unsigned)(k3 >> 14) & 0xFFu) ^ tag;
            const unsigned t4 = ((unsigned)(k4 >> 14) & 0xFFu) ^ tag;
            const unsigned t5 = ((unsigned)(k5 >> 14) & 0xFFu) ^ tag;
            const unsigned t6 = ((unsigned)(k6 >> 14) & 0xFFu) ^ tag;
            const unsigned t7 = ((unsigned)(k7 >> 14) & 0xFFu) ^ tag;
            if ((t0 | t1 | t2 | t3 | t4 | t5 | t6 | t7) == 0u) break;
        }

        if (k1 > k0) k0 = k1;  if (k3 > k2) k2 = k3;
        if (k5 > k4) k4 = k5;  if (k7 > k6) k6 = k7;
        if (k2 > k0) k0 = k2;  if (k6 > k4) k4 = k6;
        if (k4 > k0) k0 = k4;
        const unsigned widx = ((unsigned)k0 & 0x3FFFu) ^ 0x3FFFu;

        cx = sx[widx]; cy = sy[widx]; cz = sz[widx];

        if (r == 0 && t == 0) {
            g_fpsidx[b * MM + m] = (int)widx;
            centerP[(b * MM + m) * 3 + 0] = cx;
            centerP[(b * MM + m) * 3 + 1] = cy;
            centerP[(b * MM + m) * 3 + 2] = cz;
        }
    }

    asm volatile("barrier.cluster.arrive.aligned;" ::: "memory");
    asm volatile("barrier.cluster.wait.aligned;" ::: "memory");
}

/* =======================================================================
 * Kernel 2: fused ball query + gathers, query PARALLEL across 8 warps.
 * Warp w scans slice [w*2048,(w+1)*2048) collecting its first <=32
 * in-radius indices in order; slice-order concatenation + first-32 is
 * exactly global first-32-in-index-order. Merge: 8-count prefix sum,
 * scatter, pad with first. Then grouped_p (warp0) + fj/center_x gathers.
 * ===================================================================== */
__global__ void __launch_bounds__(256)
group_kernel(const float* __restrict__ p, const float* __restrict__ x,
             float* __restrict__ out)
{
    __shared__ int swlist[8][NS];
    __shared__ int swcnt[8];
    __shared__ int sidx[NS];
    __shared__ float scen[3];

    const int bm = blockIdx.x;                 /* b*256+m */
    const int b  = bm >> 8;
    const int m  = bm & (MM - 1);
    const int tid = threadIdx.x;
    const int lane = tid & 31;
    const int w = tid >> 5;

    const float* __restrict__ pb = p + (size_t)b * NN * 3;
    const float* __restrict__ centerP = out + CP_OFF;

    if (tid == 0) {
        scen[0] = centerP[bm * 3 + 0];
        scen[1] = centerP[bm * 3 + 1];
        scen[2] = centerP[bm * 3 + 2];
    }
    __syncthreads();
    const float cx = scen[0], cy = scen[1], cz = scen[2];
    const float R2 = 0.01f;   /* == f32(0.1*0.1 in double), matches ref */

    /* --- parallel slice scan: warp w covers 2048 points --- */
    int cnt = 0;
    const int sbeg = w * (NN / 8), send = sbeg + (NN / 8);
    for (int base = sbeg; base < send && cnt < NS; base += 128) {
        unsigned msk[4];
#pragma unroll
        for (int j = 0; j < 4; j++) {
            const int n = base + j * 32 + lane;
            const float dx = __fsub_rn(cx, pb[n * 3 + 0]);
            const float dy = __fsub_rn(cy, pb[n * 3 + 1]);
            const float dz = __fsub_rn(cz, pb[n * 3 + 2]);
            const float d2 = __fadd_rn(__fadd_rn(__fmul_rn(dx, dx),
                                                 __fmul_rn(dy, dy)),
                                       __fmul_rn(dz, dz));
            msk[j] = __ballot_sync(0xffffffffu, d2 < R2);
        }
#pragma unroll
        for (int j = 0; j < 4; j++) {
            const int n = base + j * 32 + lane;
            const bool in = (msk[j] >> lane) & 1u;
            const int pos = cnt + __popc(msk[j] & ((1u << lane) - 1u));
            if (in && pos < NS) swlist[w][pos] = n;
            cnt += __popc(msk[j]);
        }
    }
    if (lane == 0) swcnt[w] = (cnt > NS) ? NS : cnt;
    __syncthreads();

    /* --- merge: prefix over 8 capped counts, scatter first 32 --- */
    int pfx = 0, total = 0;
#pragma unroll
    for (int j = 0; j < 8; j++) {
        const int cj = swcnt[j];
        if (j < w) pfx += cj;
        total += cj;
    }
    if (total > NS) total = NS;
    if (lane < swcnt[w]) {
        const int pos = pfx + lane;
        if (pos < NS) sidx[pos] = swlist[w][lane];
    }
    __syncthreads();
    /* pad with first neighbor (total >= 1 always: center itself) */
    if (tid < NS && tid >= total) sidx[tid] = sidx[0];
    __syncthreads();

    /* --- grouped_p by warp 0 --- */
    if (w == 0) {
        const int myidx = sidx[lane];
        const float gx = pb[myidx * 3 + 0];
        const float gy = pb[myidx * 3 + 1];
        const float gz = pb[myidx * 3 + 2];
        float* __restrict__ gp = out + GP_OFF;
        gp[((size_t)(b * 3 + 0) * MM + m) * NS + lane] = __fsub_rn(gx, cx);
        gp[((size_t)(b * 3 + 1) * MM + m) * NS + lane] = __fsub_rn(gy, cy);
        gp[((size_t)(b * 3 + 2) * MM + m) * NS + lane] = __fsub_rn(gz, cz);
    }

    /* --- gathers: 8 channels x 32 samples per round, 16 rounds --- */
    const int s  = tid & 31;
    const int cl = tid >> 5;
    const float* __restrict__ xb = x + (size_t)b * CC * NN;
    float* __restrict__ fj = out + FJ_OFF;
    float* __restrict__ cxo = out + CX_OFF;
    const int ci = g_fpsidx[bm];
    const int myn = sidx[s];

#pragma unroll
    for (int rr = 0; rr < 16; rr++) {
        const int c = rr * 8 + cl;
        const float* __restrict__ row = xb + (size_t)c * NN;
        fj[(((size_t)(b * CC + c) * MM + m) << 5) + s] = __ldg(row + myn);
        if (s == 0)
            cxo[(size_t)(b * CC + c) * MM + m] = __ldg(row + ci);
    }
}

/* ======================================================================= */
extern "C" void kernel_launch(void* const* d_in, const int* in_sizes, int n_in,
                              void* d_out, int out_size)
{
    const float* p = (const float*)d_in[0];
    const float* x = (const float*)d_in[1];
    if (n_in >= 2 && in_sizes[0] > in_sizes[1]) {
        p = (const float*)d_in[1];
        x = (const float*)d_in[0];
    }
    float* out = (float*)d_out;

    static int configured = 0;
    if (!configured) {
        cudaFuncSetAttribute(fps_kernel,
                             cudaFuncAttributeMaxDynamicSharedMemorySize,
                             NN * 3 * (int)sizeof(float));
        configured = 1;
    }

    fps_kernel<<<BB * CLU, FPS_T, NN * 3 * sizeof(float)>>>(p, out);
    group_kernel<<<BB * MM, 256>>>(p, x, out);
}